// round 12
// baseline (speedup 1.0000x reference)
#include <cuda_runtime.h>
#include <cstdint>
#include <cstddef>

#define B_BATCH 1024
#define T_STEPS 100
#define N_IN    784
#define N_HID   100
#define N_OUT   10
#define M_TOT   (B_BATCH * T_STEPS)   // 102400

#define NKS   98          // 784 / 8 k-steps
#define NCH   49          // 784 / 16 chunks
#define NMT_T 4           // tensor: cols 0..63

// Scratch
__device__ float g_YT[(size_t)N_HID * M_TOT];   // Y^T [100][102400]
// Packed tf32 A-fragments of W1 (cols 0..63 only), k-permuted
__device__ float4 g_ApkHi[NKS * NMT_T * 32];
__device__ float4 g_ApkLo[NKS * NMT_T * 32];

// ---------------- tf32 / mma helpers ----------------
static __device__ __forceinline__ uint32_t f2tf32(float x) {
    uint32_t r;
    asm("cvt.rna.tf32.f32 %0, %1;" : "=r"(r) : "f"(x));
    return r;
}
static __device__ __forceinline__ void split_tf32(float x, uint32_t& hi, uint32_t& lo) {
    hi = f2tf32(x);
    lo = f2tf32(x - __uint_as_float(hi));
}
static __device__ __forceinline__ void mma_tf32(
    float& d0, float& d1, float& d2, float& d3,
    uint32_t a0, uint32_t a1, uint32_t a2, uint32_t a3,
    uint32_t b0, uint32_t b1)
{
    asm volatile(
        "mma.sync.aligned.m16n8k8.row.col.f32.tf32.tf32.f32 "
        "{%0,%1,%2,%3}, {%4,%5,%6,%7}, {%8,%9}, {%0,%1,%2,%3};\n"
        : "+f"(d0), "+f"(d1), "+f"(d2), "+f"(d3)
        : "r"(a0), "r"(a1), "r"(a2), "r"(a3), "r"(b0), "r"(b1));
}

// ---------------- fp32x2 helpers ----------------
static __device__ __forceinline__ unsigned long long lds_u64(uint32_t addr) {
    unsigned long long v;
    asm volatile("ld.shared.b64 %0, [%1];" : "=l"(v) : "r"(addr));
    return v;
}
static __device__ __forceinline__ unsigned long long fma2(
    unsigned long long a, unsigned long long b, unsigned long long c) {
    unsigned long long d;
    asm("fma.rn.f32x2 %0, %1, %2, %3;" : "=l"(d) : "l"(a), "l"(b), "l"(c));
    return d;
}

// ---------------- cp.async helpers ----------------
static __device__ __forceinline__ uint32_t smem_u32(const void* p) {
    uint32_t a;
    asm("{ .reg .u64 t; cvta.to.shared.u64 t, %1; cvt.u32.u64 %0, t; }"
        : "=r"(a) : "l"(p));
    return a;
}
static __device__ __forceinline__ void cp_async16(uint32_t dst, const void* src) {
    asm volatile("cp.async.ca.shared.global [%0], [%1], 16;"
                 :: "r"(dst), "l"(src) : "memory");
}
static __device__ __forceinline__ void cp_commit() {
    asm volatile("cp.async.commit_group;" ::: "memory");
}
static __device__ __forceinline__ void cp_wait1() {
    asm volatile("cp.async.wait_group 1;" ::: "memory");
}
static __device__ __forceinline__ void cp_wait0() {
    asm volatile("cp.async.wait_group 0;" ::: "memory");
}

// ============ Prep: pack W1 cols 0..63 into k-permuted tf32 fragments ======
__global__ __launch_bounds__(256) void prep_a_kernel(const float* __restrict__ W1)
{
    const int gid = blockIdx.x * 256 + threadIdx.x;
    if (gid >= NKS * NMT_T * 32) return;
    const int lane = gid & 31;
    const int mt   = (gid >> 5) % NMT_T;
    const int s2   = (gid >> 5) / NMT_T;
    const int q = lane >> 2, r = lane & 3;
    const int c  = s2 >> 1, ph = s2 & 1;

    const int kA = 16 * c + 4 * r + 2 * ph;
    const int kB = kA + 1;
    const int n0 = mt * 16 + q;     // < 64
    const int n1 = n0 + 8;

    const float v0 = W1[(size_t)n0 * N_IN + kA];
    const float v1 = W1[(size_t)n1 * N_IN + kA];
    const float v2 = W1[(size_t)n0 * N_IN + kB];
    const float v3 = W1[(size_t)n1 * N_IN + kB];

    uint32_t h0, l0, h1, l1, h2, l2, h3, l3;
    split_tf32(v0, h0, l0); split_tf32(v1, h1, l1);
    split_tf32(v2, h2, l2); split_tf32(v3, h3, l3);

    float4 fh, fl;
    fh.x = __uint_as_float(h0); fh.y = __uint_as_float(h1);
    fh.z = __uint_as_float(h2); fh.w = __uint_as_float(h3);
    fl.x = __uint_as_float(l0); fl.y = __uint_as_float(l1);
    fl.z = __uint_as_float(l2); fl.w = __uint_as_float(l3);

    const int idx = (s2 * NMT_T + mt) * 32 + lane;
    g_ApkHi[idx] = fh;
    g_ApkLo[idx] = fl;
}

// ==================== tensor flavor: cols 0..63 (tf32x3) ====================
static __device__ __forceinline__ void tensor_block(
    int tb, const float* __restrict__ X, float4* As)
{
    constexpr int CH = 2 * NMT_T * 32;   // 256 float4 per (hi|lo) per chunk
    const int tid  = threadIdx.x;
    const int warp = tid >> 5;
    const int lane = tid & 31;
    const int q = lane >> 2, r = lane & 3;
    const int m0w = tb * 128 + warp * 16;

    float acc[NMT_T][2][4];
#pragma unroll
    for (int mt = 0; mt < NMT_T; ++mt)
#pragma unroll
        for (int nt = 0; nt < 2; ++nt)
#pragma unroll
            for (int i = 0; i < 4; ++i) acc[mt][nt][i] = 0.f;

    const float4* xr[2];
#pragma unroll
    for (int nt = 0; nt < 2; ++nt)
        xr[nt] = reinterpret_cast<const float4*>(X)
               + (size_t)(m0w + nt * 8 + q) * (N_IN / 4) + r;

    const uint32_t as_base = smem_u32(As);

    auto stage = [&](int cc, int b) {
        const uint32_t dst = as_base + (uint32_t)(b * 2 * CH) * 16u;
        const float4* srcH = g_ApkHi + (size_t)cc * CH;
        const float4* srcL = g_ApkLo + (size_t)cc * CH;
#pragma unroll
        for (int i = tid; i < CH; i += 256) {
            cp_async16(dst + (uint32_t)i * 16u,        srcH + i);
            cp_async16(dst + (uint32_t)(CH + i) * 16u, srcL + i);
        }
        cp_commit();
    };

    stage(0, 0);
    float4 V[2], Vn[2];
#pragma unroll
    for (int nt = 0; nt < 2; ++nt) V[nt] = xr[nt][0];

    for (int c = 0; c < NCH; ++c) {
        const int b = c & 1;
        if (c + 1 < NCH) { stage(c + 1, b ^ 1); cp_wait1(); }
        else             { cp_wait0(); }
        __syncthreads();

        const int cn = (c + 1 < NCH) ? c + 1 : c;
#pragma unroll
        for (int nt = 0; nt < 2; ++nt) Vn[nt] = xr[nt][(size_t)cn * 4];

        const float4* Ab = As + b * 2 * CH;

#pragma unroll
        for (int ph = 0; ph < 2; ++ph) {
            uint32_t bh[2][2], bl[2][2];
#pragma unroll
            for (int nt = 0; nt < 2; ++nt) {
                const float x0 = ph ? V[nt].z : V[nt].x;
                const float x1 = ph ? V[nt].w : V[nt].y;
                split_tf32(x0, bh[nt][0], bl[nt][0]);
                split_tf32(x1, bh[nt][1], bl[nt][1]);
            }

#pragma unroll
            for (int mt = 0; mt < NMT_T; ++mt) {
                const float4 ah4 = Ab[(ph * NMT_T + mt) * 32 + lane];
                const float4 al4 = Ab[CH + (ph * NMT_T + mt) * 32 + lane];
                const uint32_t ah[4] = {
                    __float_as_uint(ah4.x), __float_as_uint(ah4.y),
                    __float_as_uint(ah4.z), __float_as_uint(ah4.w) };
                const uint32_t al[4] = {
                    __float_as_uint(al4.x), __float_as_uint(al4.y),
                    __float_as_uint(al4.z), __float_as_uint(al4.w) };
#pragma unroll
                for (int nt = 0; nt < 2; ++nt)
                    mma_tf32(acc[mt][nt][0], acc[mt][nt][1],
                             acc[mt][nt][2], acc[mt][nt][3],
                             ah[0], ah[1], ah[2], ah[3], bh[nt][0], bh[nt][1]);
#pragma unroll
                for (int nt = 0; nt < 2; ++nt)
                    mma_tf32(acc[mt][nt][0], acc[mt][nt][1],
                             acc[mt][nt][2], acc[mt][nt][3],
                             ah[0], ah[1], ah[2], ah[3], bl[nt][0], bl[nt][1]);
#pragma unroll
                for (int nt = 0; nt < 2; ++nt)
                    mma_tf32(acc[mt][nt][0], acc[mt][nt][1],
                             acc[mt][nt][2], acc[mt][nt][3],
                             al[0], al[1], al[2], al[3], bh[nt][0], bh[nt][1]);
            }
        }

#pragma unroll
        for (int nt = 0; nt < 2; ++nt) V[nt] = Vn[nt];
        __syncthreads();
    }

#pragma unroll
    for (int mt = 0; mt < NMT_T; ++mt) {
        const int n0 = mt * 16 + q;   // < 64
#pragma unroll
        for (int nt = 0; nt < 2; ++nt) {
            const int m = m0w + nt * 8 + 2 * r;
            *reinterpret_cast<float2*>(g_YT + (size_t)n0 * M_TOT + m) =
                make_float2(acc[mt][nt][0], acc[mt][nt][1]);
            *reinterpret_cast<float2*>(g_YT + (size_t)(n0 + 8) * M_TOT + m) =
                make_float2(acc[mt][nt][2], acc[mt][nt][3]);
        }
    }
}

// ==================== fp32 flavor: cols 64..99 (exact, FFMA2) ===============
// 18 pairs (64+q, 82+q), q = x + 6j. Compute threads: x in 0..5, y in 0..31.
#define BKf  16
#define XSTR 133
#define WSTR 19

static __device__ __forceinline__ void fp32_block(
    int fb, const float* __restrict__ X, const float* __restrict__ W1,
    float2* Xs, float2* Ws)
{
    const int tid = threadIdx.x;
    const bool active = (tid < 192);
    const int x = tid % 6;
    const int y = tid / 6;
    const int m0 = fb * 128;

    unsigned long long acc[4][3];
#pragma unroll
    for (int r = 0; r < 4; ++r)
#pragma unroll
        for (int j = 0; j < 3; ++j) acc[r][j] = 0ull;

    // X loader: 128 rows x 4 f4-slots = 512 units, two passes
    const int xr1 = tid >> 2, xs1 = tid & 3;
    const int xu2 = tid + 256;
    const int xr2 = xu2 >> 2, xs2 = xu2 & 3;
    // W loader: rows 64..99 (36) x 4 slots = 144 units
    const bool pw = (tid < 144);
    const int widx = tid >> 2;      // 0..35
    const int wslot = tid & 3;
    const int wrow = 64 + widx;

    const float4* X4 = reinterpret_cast<const float4*>(X);
    const float4* W4 = reinterpret_cast<const float4*>(W1);
    const size_t xoff1 = (size_t)(m0 + xr1) * (N_IN / 4) + xs1;
    const size_t xoff2 = (size_t)(m0 + xr2) * (N_IN / 4) + xs2;
    const size_t woff  = (size_t)(pw ? wrow : 64) * (N_IN / 4) + wslot;

    const uint32_t xs_base = smem_u32(Xs);
    const uint32_t ws_base = smem_u32(Ws);

    for (int kc = 0; kc < N_IN / BKf; ++kc) {   // 49 chunks of 16 k
        float4 xa = X4[xoff1 + (size_t)kc * 4];
        float4 xb = X4[xoff2 + (size_t)kc * 4];
        float4 wv = make_float4(0.f, 0.f, 0.f, 0.f);
        if (pw) wv = W4[woff + (size_t)kc * 4];

        __syncthreads();

        {
            float v[4] = {xa.x, xa.y, xa.z, xa.w};
#pragma unroll
            for (int j = 0; j < 4; ++j)
                Xs[(xs1 * 4 + j) * XSTR + xr1] = make_float2(v[j], v[j]);
        }
        {
            float v[4] = {xb.x, xb.y, xb.z, xb.w};
#pragma unroll
            for (int j = 0; j < 4; ++j)
                Xs[(xs2 * 4 + j) * XSTR + xr2] = make_float2(v[j], v[j]);
        }
        if (pw) {
            float v[4] = {wv.x, wv.y, wv.z, wv.w};
            const int q    = (widx < 18) ? widx : widx - 18;
            const int half = (widx < 18) ? 0 : 1;
#pragma unroll
            for (int j = 0; j < 4; ++j)
                reinterpret_cast<float*>(&Ws[(wslot * 4 + j) * WSTR + q])[half] = v[j];
        }
        __syncthreads();

        if (active) {
#pragma unroll
            for (int k = 0; k < BKf; ++k) {
                const uint32_t xaddr = xs_base + (uint32_t)(k * XSTR + y) * 8u;
                const uint32_t waddr = ws_base + (uint32_t)(k * WSTR + x) * 8u;
                unsigned long long a[4], bb[3];
#pragma unroll
                for (int r = 0; r < 4; ++r)
                    a[r] = lds_u64(xaddr + (uint32_t)(32 * r) * 8u);
#pragma unroll
                for (int j = 0; j < 3; ++j)
                    bb[j] = lds_u64(waddr + (uint32_t)(6 * j) * 8u);
#pragma unroll
                for (int r = 0; r < 4; ++r)
#pragma unroll
                    for (int j = 0; j < 3; ++j)
                        acc[r][j] = fma2(a[r], bb[j], acc[r][j]);
            }
        }
    }

    if (active) {
#pragma unroll
        for (int r = 0; r < 4; ++r) {
            const int m = m0 + y + 32 * r;
#pragma unroll
            for (int j = 0; j < 3; ++j) {
                const int q = x + 6 * j;
                const float lo = __uint_as_float((uint32_t)(acc[r][j] & 0xffffffffull));
                const float hi = __uint_as_float((uint32_t)(acc[r][j] >> 32));
                g_YT[(size_t)(64 + q) * M_TOT + m] = lo;
                g_YT[(size_t)(82 + q) * M_TOT + m] = hi;
            }
        }
    }
}

// ==================== hybrid dispatcher ====================
// wave-1 friendly: bids {0..147}=T, {148..295}=T, {296..443}=F -> each SM (T,T,F)
__global__ __launch_bounds__(256, 3) void gemm1_hybrid_kernel(
    const float* __restrict__ X, const float* __restrict__ W1)
{
    __shared__ __align__(16) char sraw[20480];

    const int bid = blockIdx.x;
    int tb = -1, fb = -1;
    if (bid < 296)      tb = bid;
    else if (bid < 444) fb = bid - 296;
    else {
        const int r = bid - 444;          // 0..1155
        if (r < 1008) {
            if ((r & 1) == 0) tb = 296 + (r >> 1);
            else              fb = 148 + (r >> 1);
        } else {
            fb = 652 + (r - 1008);
        }
    }

    if (tb >= 0)
        tensor_block(tb, X, reinterpret_cast<float4*>(sraw));
    else
        fp32_block(fb, X, W1,
                   reinterpret_cast<float2*>(sraw),
                   reinterpret_cast<float2*>(sraw + 17024));
}

// ============ Fused SNN: scan1 + gemm2 + scan2, one block per batch b ======
__global__ __launch_bounds__(128) void snn_fused_kernel(
    const float* __restrict__ w_syn1, const float* __restrict__ b1,
    const float* __restrict__ w_syn2, const float* __restrict__ W2,
    const float* __restrict__ b2, float* __restrict__ out)
{
    __shared__ float    w2s[N_HID * N_OUT];    // [h*10+o]
    __shared__ uint32_t spw[N_HID * 4];        // spike bits [h][word]
    __shared__ float    h2s[N_OUT * T_STEPS];  // [o*100+t]

    const int b   = blockIdx.x;
    const int tid = threadIdx.x;

    for (int i = tid; i < N_HID * N_OUT; i += 128) {
        const int o = i / N_HID, h = i % N_HID;
        w2s[h * N_OUT + o] = W2[i];
    }

    // ---- phase 1: layer-1 scan, thread = h ----
    if (tid < N_HID) {
        const int h = tid;
        const float inv1 = 1.f / (1.f + expf(-w_syn1[0]));
        const float bh = b1[h];
        const float* Yp = g_YT + (size_t)h * M_TOT + (size_t)b * T_STEPS;

        float hs = 0.f, v = 0.f;
        uint32_t w[4] = {0u, 0u, 0u, 0u};
#pragma unroll 1
        for (int i = 0; i < T_STEPS / 4; ++i) {
            const float4 yv = *reinterpret_cast<const float4*>(Yp + i * 4);
            const float ya[4] = {yv.x, yv.y, yv.z, yv.w};
#pragma unroll
            for (int j = 0; j < 4; ++j) {
                hs = (hs - hs * inv1) + ya[j];          // SynapseFilter 1
                const float h1 = hs + bh;
                v = v + (h1 - v) * 0.5f;                // LIF decay (tau=2)
                const int t = i * 4 + j;
                if (v >= 1.0f) {
                    w[t >> 5] |= (1u << (t & 31));
                    v = 0.f;                            // hard reset
                }
            }
        }
#pragma unroll
        for (int k = 0; k < 4; ++k) spw[h * 4 + k] = w[k];
    }
    __syncthreads();

    // ---- phase 2: H2[o][t] = sum_h bit(h,t) * W2[o,h], thread = t ----
    if (tid < T_STEPS) {
        const int t = tid;
        const int wrd = t >> 5, bit = t & 31;
        float acc[N_OUT];
#pragma unroll
        for (int o = 0; o < N_OUT; ++o) acc[o] = 0.f;
#pragma unroll 4
        for (int h = 0; h < N_HID; ++h) {
            const uint32_t word = spw[h * 4 + wrd];
            const float v = (float)((word >> bit) & 1u);
#pragma unroll
            for (int o = 0; o < N_OUT; ++o)
                acc[o] = fmaf(v, w2s[h * N_OUT + o], acc[o]);
        }
#pragma unroll
        for (int o = 0; o < N_OUT; ++o) h2s[o * T_STEPS + t] = acc[o];
    }
    __syncthreads();

    // ---- phase 3: layer-2 scan, thread = o ----
    if (tid < N_OUT) {
        const int o = tid;
        const float inv2 = 1.f / (1.f + expf(-w_syn2[0]));
        const float bo = b2[o];
        const float* hp = h2s + o * T_STEPS;

        float hs = 0.f, v = 0.f;
#pragma unroll 4
        for (int t = 0; t < T_STEPS; ++t) {
            const float p = hp[t];
            hs = (hs - hs * inv2) + p;   // SynapseFilter 2
            const float h2 = hs + bo;
            v = v + (h2 - v) * 0.5f;     // LIF 2 (soft reset @thr 0 -> no-op)
        }
        out[b * N_OUT + o] = v;
    }
}

// ---------------- entry ----------------
extern "C" void kernel_launch(void* const* d_in, const int* in_sizes, int n_in,
                              void* d_out, int out_size) {
    const float* x   = (const float*)d_in[0];  // [1024, 100, 784]
    const float* w1s = (const float*)d_in[1];
    const float* W1  = (const float*)d_in[2];  // [100, 784]
    const float* b1  = (const float*)d_in[3];
    const float* w2s = (const float*)d_in[4];
    const float* W2  = (const float*)d_in[5];  // [10, 100]
    const float* b2  = (const float*)d_in[6];
    float* out = (float*)d_out;                // [1024, 10]

    prep_a_kernel<<<(NKS * NMT_T * 32 + 255) / 256, 256>>>(W1);
    gemm1_hybrid_kernel<<<1600, 256>>>(x, W1);   // 800 tensor + 800 fp32 blocks
    snn_fused_kernel<<<B_BATCH, 128>>>(w1s, b1, w2s, W2, b2, out);
}

// round 13
// speedup vs baseline: 2.0917x; 2.0917x over previous
#include <cuda_runtime.h>
#include <cuda_fp16.h>
#include <cstdint>
#include <cstddef>

#define B_BATCH 1024
#define T_STEPS 100
#define N_IN    784
#define N_HID   100
#define N_OUT   10
#define M_TOT   (B_BATCH * T_STEPS)   // 102400

#define NCHP  50          // k16 chunks, padded (chunk 49 = zeros)
#define NCHV  49          // valid chunks
#define NST   25          // stages of 2 chunks

// Scratch
__device__ float g_YT[(size_t)N_HID * M_TOT];   // Y^T [100][102400]
// Packed fp16 A-fragments of W1 (hi/mid), k-permuted, split by column half.
// Layout: [chunk][mt][lane] -> uint4 (a0,a1,a2,a3 as fp16x2)
__device__ uint4 g_AH0[NCHP * 4 * 32];
__device__ uint4 g_AM0[NCHP * 4 * 32];
__device__ uint4 g_AH1[NCHP * 3 * 32];
__device__ uint4 g_AM1[NCHP * 3 * 32];

// ---------------- fp16 helpers ----------------
static __device__ __forceinline__ uint32_t packh2(__half a, __half b) {
    __half2 h = __halves2half2(a, b);
    return *reinterpret_cast<uint32_t*>(&h);
}
static __device__ __forceinline__ void split_f16(float x, __half& h, __half& m) {
    h = __float2half_rn(x);
    m = __float2half_rn(x - __half2float(h));
}
static __device__ __forceinline__ void mma_f16(
    float& d0, float& d1, float& d2, float& d3,
    uint32_t a0, uint32_t a1, uint32_t a2, uint32_t a3,
    uint32_t b0, uint32_t b1)
{
    asm volatile(
        "mma.sync.aligned.m16n8k16.row.col.f32.f16.f16.f32 "
        "{%0,%1,%2,%3}, {%4,%5,%6,%7}, {%8,%9}, {%0,%1,%2,%3};\n"
        : "+f"(d0), "+f"(d1), "+f"(d2), "+f"(d3)
        : "r"(a0), "r"(a1), "r"(a2), "r"(a3), "r"(b0), "r"(b1));
}

// ---------------- cp.async helpers ----------------
static __device__ __forceinline__ uint32_t smem_u32(const void* p) {
    uint32_t a;
    asm("{ .reg .u64 t; cvta.to.shared.u64 t, %1; cvt.u32.u64 %0, t; }"
        : "=r"(a) : "l"(p));
    return a;
}
static __device__ __forceinline__ void cp_async16(uint32_t dst, const void* src) {
    asm volatile("cp.async.ca.shared.global [%0], [%1], 16;"
                 :: "r"(dst), "l"(src) : "memory");
}
static __device__ __forceinline__ void cp_commit() {
    asm volatile("cp.async.commit_group;" ::: "memory");
}
static __device__ __forceinline__ void cp_wait1() {
    asm volatile("cp.async.wait_group 1;" ::: "memory");
}
static __device__ __forceinline__ void cp_wait0() {
    asm volatile("cp.async.wait_group 0;" ::: "memory");
}

// ============ Prep: pack W1 into k-permuted fp16 hi/mid A-fragments ========
// chunk c covers real k [16c, 16c+16). Lane r: frag k {2r,2r+1} -> real kb+{0,1},
// frag {2r+8,2r+9} -> real kb+{2,3}, kb = 16c+4r.
__global__ __launch_bounds__(256) void prep_a_kernel(const float* __restrict__ W1)
{
    const int gid = blockIdx.x * 256 + threadIdx.x;
    if (gid >= NCHP * 7 * 32) return;
    const int lane = gid & 31;
    const int mt   = (gid >> 5) % 7;
    const int c    = (gid >> 5) / 7;
    const int q = lane >> 2, r = lane & 3;
    const int kb = 16 * c + 4 * r;
    const int n0 = mt * 16 + q;
    const int n1 = n0 + 8;
    const bool kv = (c < NCHV);   // chunk 49: zeros

    float w0a = 0.f, w0b = 0.f, w0c = 0.f, w0d = 0.f;
    float w1a = 0.f, w1b = 0.f, w1c = 0.f, w1d = 0.f;
    if (kv) {
        if (n0 < N_HID) {
            w0a = W1[(size_t)n0 * N_IN + kb];
            w0b = W1[(size_t)n0 * N_IN + kb + 1];
            w0c = W1[(size_t)n0 * N_IN + kb + 2];
            w0d = W1[(size_t)n0 * N_IN + kb + 3];
        }
        if (n1 < N_HID) {
            w1a = W1[(size_t)n1 * N_IN + kb];
            w1b = W1[(size_t)n1 * N_IN + kb + 1];
            w1c = W1[(size_t)n1 * N_IN + kb + 2];
            w1d = W1[(size_t)n1 * N_IN + kb + 3];
        }
    }

    __half h, m;
    __half h0a, m0a, h0b, m0b, h0c, m0c, h0d, m0d;
    __half h1a, m1a, h1b, m1b, h1c, m1c, h1d, m1d;
    split_f16(w0a, h0a, m0a); split_f16(w0b, h0b, m0b);
    split_f16(w0c, h0c, m0c); split_f16(w0d, h0d, m0d);
    split_f16(w1a, h1a, m1a); split_f16(w1b, h1b, m1b);
    split_f16(w1c, h1c, m1c); split_f16(w1d, h1d, m1d);
    (void)h; (void)m;

    uint4 H, M;
    H.x = packh2(h0a, h0b);   // a0: row n0, real k kb,kb+1
    H.y = packh2(h1a, h1b);   // a1: row n1
    H.z = packh2(h0c, h0d);   // a2: row n0, real k kb+2,kb+3
    H.w = packh2(h1c, h1d);   // a3: row n1
    M.x = packh2(m0a, m0b);
    M.y = packh2(m1a, m1b);
    M.z = packh2(m0c, m0d);
    M.w = packh2(m1c, m1d);

    if (mt < 4) {
        const int idx = (c * 4 + mt) * 32 + lane;
        g_AH0[idx] = H;
        g_AM0[idx] = M;
    } else {
        const int idx = (c * 3 + (mt - 4)) * 32 + lane;
        g_AH1[idx] = H;
        g_AM1[idx] = M;
    }
}

// ============ GEMM1: YT[n][m] = sum_k W1[n,k] X[m,k] (fp16x3) ============
// grid (800, 2): x = 128-row m-block, y = column half. 256 thr, 3 CTA/SM.
// A staged (2 chunks / stage) via cp.async double buffer; X prefetch 1 chunk.
template <int NMTY, int MTBASE>
static __device__ __forceinline__ void gemm_half(
    const float* __restrict__ X,
    const uint4* __restrict__ Ah, const uint4* __restrict__ Am,
    uint4* As)
{
    constexpr int CHPC = NMTY * 32;       // uint4 per chunk per part
    const int tid  = threadIdx.x;
    const int warp = tid >> 5;
    const int lane = tid & 31;
    const int q = lane >> 2, r = lane & 3;
    const int m0w = blockIdx.x * 128 + warp * 16;

    float acc[NMTY][2][4];
#pragma unroll
    for (int mt = 0; mt < NMTY; ++mt)
#pragma unroll
        for (int nt = 0; nt < 2; ++nt)
#pragma unroll
            for (int i = 0; i < 4; ++i) acc[mt][nt][i] = 0.f;

    // X float4 pointer: lane reads X[m][16c+4r .. +3]
    const float4* xr[2];
#pragma unroll
    for (int nt = 0; nt < 2; ++nt)
        xr[nt] = reinterpret_cast<const float4*>(X)
               + (size_t)(m0w + nt * 8 + q) * (N_IN / 4) + r;

    const uint32_t as_base = smem_u32(As);

    // stage = 2 chunks (h then m), buffer b
    auto stage = [&](int st, int b) {
        const uint32_t dst = as_base + (uint32_t)(b * 4 * CHPC) * 16u;
        const uint4* srcH = Ah + (size_t)(2 * st) * CHPC;
        const uint4* srcM = Am + (size_t)(2 * st) * CHPC;
#pragma unroll
        for (int i = tid; i < 2 * CHPC; i += 256) {
            cp_async16(dst + (uint32_t)i * 16u,                srcH + i);
            cp_async16(dst + (uint32_t)(2 * CHPC + i) * 16u,   srcM + i);
        }
        cp_commit();
    };

    stage(0, 0);
    float4 V[2], Vn[2];
#pragma unroll
    for (int nt = 0; nt < 2; ++nt) V[nt] = xr[nt][0];

    for (int st = 0; st < NST; ++st) {
        const int b = st & 1;
        if (st + 1 < NST) { stage(st + 1, b ^ 1); cp_wait1(); }
        else              { cp_wait0(); }
        __syncthreads();

        const uint4* Ab = As + b * 4 * CHPC;

#pragma unroll
        for (int i = 0; i < 2; ++i) {
            const int ch = 2 * st + i;
            // prefetch X for next chunk
            const int cn = ch + 1;
#pragma unroll
            for (int nt = 0; nt < 2; ++nt)
                Vn[nt] = (cn < NCHV) ? xr[nt][(size_t)cn * 4]
                                     : make_float4(0.f, 0.f, 0.f, 0.f);

            // B fragments: split X into fp16 hi/mid
            uint32_t bh[2][2], bm[2][2];
#pragma unroll
            for (int nt = 0; nt < 2; ++nt) {
                __half h0, m0, h1, m1, h2, m2, h3, m3;
                split_f16(V[nt].x, h0, m0);
                split_f16(V[nt].y, h1, m1);
                split_f16(V[nt].z, h2, m2);
                split_f16(V[nt].w, h3, m3);
                bh[nt][0] = packh2(h0, h1);
                bh[nt][1] = packh2(h2, h3);
                bm[nt][0] = packh2(m0, m1);
                bm[nt][1] = packh2(m2, m3);
            }

#pragma unroll
            for (int mt = 0; mt < NMTY; ++mt) {
                const uint4 AH = Ab[i * CHPC + mt * 32 + lane];
                const uint4 AM = Ab[2 * CHPC + i * CHPC + mt * 32 + lane];
                // pass 1: Ah * Bh
#pragma unroll
                for (int nt = 0; nt < 2; ++nt)
                    mma_f16(acc[mt][nt][0], acc[mt][nt][1],
                            acc[mt][nt][2], acc[mt][nt][3],
                            AH.x, AH.y, AH.z, AH.w, bh[nt][0], bh[nt][1]);
                // pass 2: Ah * Bm
#pragma unroll
                for (int nt = 0; nt < 2; ++nt)
                    mma_f16(acc[mt][nt][0], acc[mt][nt][1],
                            acc[mt][nt][2], acc[mt][nt][3],
                            AH.x, AH.y, AH.z, AH.w, bm[nt][0], bm[nt][1]);
                // pass 3: Am * Bh
#pragma unroll
                for (int nt = 0; nt < 2; ++nt)
                    mma_f16(acc[mt][nt][0], acc[mt][nt][1],
                            acc[mt][nt][2], acc[mt][nt][3],
                            AM.x, AM.y, AM.z, AM.w, bh[nt][0], bh[nt][1]);
            }

#pragma unroll
            for (int nt = 0; nt < 2; ++nt) V[nt] = Vn[nt];
        }
        __syncthreads();
    }

    // epilogue -> YT[n][m]  (C layout of m16n8: same as k8 variant)
#pragma unroll
    for (int mt = 0; mt < NMTY; ++mt) {
        const int n0 = (MTBASE + mt) * 16 + q;
#pragma unroll
        for (int nt = 0; nt < 2; ++nt) {
            const int m = m0w + nt * 8 + 2 * r;
            if (n0 < N_HID)
                *reinterpret_cast<float2*>(g_YT + (size_t)n0 * M_TOT + m) =
                    make_float2(acc[mt][nt][0], acc[mt][nt][1]);
            if (n0 + 8 < N_HID)
                *reinterpret_cast<float2*>(g_YT + (size_t)(n0 + 8) * M_TOT + m) =
                    make_float2(acc[mt][nt][2], acc[mt][nt][3]);
        }
    }
}

__global__ __launch_bounds__(256, 3) void gemm1_mma_kernel(const float* __restrict__ X)
{
    // max half (NMTY=4): 2 buffers x 2 parts x 2 chunks x 128 uint4 = 16 KB
    __shared__ uint4 As[2 * 4 * (4 * 32)];
    if (blockIdx.y == 0)
        gemm_half<4, 0>(X, g_AH0, g_AM0, As);
    else
        gemm_half<3, 4>(X, g_AH1, g_AM1, As);
}

// ============ Fused SNN: scan1 + gemm2 + scan2, one block per batch b ======
__global__ __launch_bounds__(128) void snn_fused_kernel(
    const float* __restrict__ w_syn1, const float* __restrict__ b1,
    const float* __restrict__ w_syn2, const float* __restrict__ W2,
    const float* __restrict__ b2, float* __restrict__ out)
{
    __shared__ float    w2s[N_HID * N_OUT];    // [h*10+o]
    __shared__ uint32_t spw[N_HID * 4];        // spike bits [h][word]
    __shared__ float    h2s[N_OUT * T_STEPS];  // [o*100+t]

    const int b   = blockIdx.x;
    const int tid = threadIdx.x;

    for (int i = tid; i < N_HID * N_OUT; i += 128) {
        const int o = i / N_HID, h = i % N_HID;
        w2s[h * N_OUT + o] = W2[i];
    }

    // ---- phase 1: layer-1 scan, thread = h ----
    if (tid < N_HID) {
        const int h = tid;
        const float inv1 = 1.f / (1.f + expf(-w_syn1[0]));
        const float bh = b1[h];
        const float* Yp = g_YT + (size_t)h * M_TOT + (size_t)b * T_STEPS;

        float hs = 0.f, v = 0.f;
        uint32_t w[4] = {0u, 0u, 0u, 0u};
#pragma unroll 1
        for (int i = 0; i < T_STEPS / 4; ++i) {
            const float4 yv = *reinterpret_cast<const float4*>(Yp + i * 4);
            const float ya[4] = {yv.x, yv.y, yv.z, yv.w};
#pragma unroll
            for (int j = 0; j < 4; ++j) {
                hs = (hs - hs * inv1) + ya[j];          // SynapseFilter 1
                const float h1 = hs + bh;
                v = v + (h1 - v) * 0.5f;                // LIF decay (tau=2)
                const int t = i * 4 + j;
                if (v >= 1.0f) {
                    w[t >> 5] |= (1u << (t & 31));
                    v = 0.f;                            // hard reset
                }
            }
        }
#pragma unroll
        for (int k = 0; k < 4; ++k) spw[h * 4 + k] = w[k];
    }
    __syncthreads();

    // ---- phase 2: H2[o][t] = sum_h bit(h,t) * W2[o,h], thread = t ----
    if (tid < T_STEPS) {
        const int t = tid;
        const int wrd = t >> 5, bit = t & 31;
        float acc[N_OUT];
#pragma unroll
        for (int o = 0; o < N_OUT; ++o) acc[o] = 0.f;
#pragma unroll 4
        for (int h = 0; h < N_HID; ++h) {
            const uint32_t word = spw[h * 4 + wrd];
            const float v = (float)((word >> bit) & 1u);
#pragma unroll
            for (int o = 0; o < N_OUT; ++o)
                acc[o] = fmaf(v, w2s[h * N_OUT + o], acc[o]);
        }
#pragma unroll
        for (int o = 0; o < N_OUT; ++o) h2s[o * T_STEPS + t] = acc[o];
    }
    __syncthreads();

    // ---- phase 3: layer-2 scan, thread = o ----
    if (tid < N_OUT) {
        const int o = tid;
        const float inv2 = 1.f / (1.f + expf(-w_syn2[0]));
        const float bo = b2[o];
        const float* hp = h2s + o * T_STEPS;

        float hs = 0.f, v = 0.f;
#pragma unroll 4
        for (int t = 0; t < T_STEPS; ++t) {
            const float p = hp[t];
            hs = (hs - hs * inv2) + p;   // SynapseFilter 2
            const float h2 = hs + bo;
            v = v + (h2 - v) * 0.5f;     // LIF 2 (soft reset @thr 0 -> no-op)
        }
        out[b * N_OUT + o] = v;
    }
}

// ---------------- entry ----------------
extern "C" void kernel_launch(void* const* d_in, const int* in_sizes, int n_in,
                              void* d_out, int out_size) {
    const float* x   = (const float*)d_in[0];  // [1024, 100, 784]
    const float* w1s = (const float*)d_in[1];
    const float* W1  = (const float*)d_in[2];  // [100, 784]
    const float* b1  = (const float*)d_in[3];
    const float* w2s = (const float*)d_in[4];
    const float* W2  = (const float*)d_in[5];  // [10, 100]
    const float* b2  = (const float*)d_in[6];
    float* out = (float*)d_out;                // [1024, 10]

    prep_a_kernel<<<(NCHP * 7 * 32 + 255) / 256, 256>>>(W1);
    gemm1_mma_kernel<<<dim3(M_TOT / 128, 2), 256>>>(x);
    snn_fused_kernel<<<B_BATCH, 128>>>(w1s, b1, w2s, W2, b2, out);
}